// round 7
// baseline (speedup 1.0000x reference)
#include <cuda_runtime.h>
#include <cstdint>

#define BB 256
#define SS 512
#define N_IN 2048
#define N_OUT 512
#define HH 30
#define ROWS (BB*SS)   // 131072

// ---------------- device scratch ----------------
__device__ float g_flat[(size_t)ROWS * HH];
__device__ float g_z0x[(size_t)ROWS * 128];   // layer0 input-gate preactivations (padded 120->128)
__device__ float g_partial[1024 * 64];
__device__ float g_mu[HH];
__device__ float g_rstd[HH];
// pre-converted weights: [n][k][2] = (tf32hi, tf32lo)
__device__ uint32_t g_w1t[32 * N_IN * 2];     // 512 KB
__device__ uint32_t g_wot[N_OUT * 32 * 2];    // 128 KB
__device__ uint32_t g_wz[128 * 32 * 2];       // BN-folded Wih0, 32 KB
__device__ float g_c0v[128];                  // folded bias for z0x

// ---------------- helpers ----------------
__device__ __forceinline__ uint32_t cvt_tf32(float f) {
    uint32_t u; asm("cvt.rna.tf32.f32 %0, %1;" : "=r"(u) : "f"(f)); return u;
}
__device__ __forceinline__ void mma_tf32(float& c0, float& c1, float& c2, float& c3,
                                         uint32_t a0, uint32_t a1, uint32_t a2, uint32_t a3,
                                         uint32_t b0, uint32_t b1) {
    asm volatile(
        "mma.sync.aligned.m16n8k8.row.col.f32.tf32.tf32.f32 "
        "{%0,%1,%2,%3},{%4,%5,%6,%7},{%8,%9},{%0,%1,%2,%3};"
        : "+f"(c0), "+f"(c1), "+f"(c2), "+f"(c3)
        : "r"(a0), "r"(a1), "r"(a2), "r"(a3), "r"(b0), "r"(b1));
}
__device__ __forceinline__ float htanh(float x) {
    float r; asm("tanh.approx.f32 %0,%1;" : "=f"(r) : "f"(x)); return r;
}
__device__ __forceinline__ float hsig(float x) {
    return fmaf(htanh(x * 0.5f), 0.5f, 0.5f);
}

// ---------------- prep: convert W1/Wout to tf32 hi/lo interleaved ----------
__global__ __launch_bounds__(256)
void prep_w_kernel(const float* __restrict__ W1, const float* __restrict__ Wout)
{
    int i = blockIdx.x * 256 + threadIdx.x;
    if (i < 32 * N_IN) {
        int k = i >> 5, n = i & 31;
        float w = (n < HH) ? W1[(size_t)k * HH + n] : 0.f;
        uint32_t hb = cvt_tf32(w);
        float lo = w - __uint_as_float(hb);
        g_w1t[(n * N_IN + k) * 2]     = hb;
        g_w1t[(n * N_IN + k) * 2 + 1] = cvt_tf32(lo);
    }
    int j = i - 32 * N_IN;
    if (j >= 0 && j < N_OUT * 32) {
        int n = j >> 5, k = j & 31;
        float w = (k < HH) ? Wout[(size_t)k * N_OUT + n] : 0.f;
        uint32_t hb = cvt_tf32(w);
        float lo = w - __uint_as_float(hb);
        g_wot[(n * 32 + k) * 2]     = hb;
        g_wot[(n * 32 + k) * 2 + 1] = cvt_tf32(lo);
    }
}

// ================= fc1: tf32 mma.sync, double-buffered =================
#define FC1_A_FL (2*128*36)
#define FC1_B_FL (2*32*36*2)
#define FC1_SMEM_BYTES ((FC1_A_FL + FC1_B_FL + 32 + 512) * 4)

__global__ __launch_bounds__(256)
void fc1_mma_kernel(const float* __restrict__ x, const float* __restrict__ b1)
{
    extern __shared__ __align__(16) float sm[];
    float*  a_s    = sm;                               // [2][128][36]
    float2* b_s    = (float2*)(sm + FC1_A_FL);         // [2][32][36]
    float*  bias_s = sm + FC1_A_FL + FC1_B_FL;         // [32]
    float*  red    = bias_s + 32;                      // [2][256]

    const int tid  = threadIdx.x;
    const int wid  = tid >> 5;
    const int lane = tid & 31;
    const int g    = lane >> 2;
    const int tg   = lane & 3;
    const size_t rowBase = (size_t)blockIdx.x * 128;

    if (tid < 32) bias_s[tid] = (tid < HH) ? b1[tid] : 0.f;

    float c[4][4];
    #pragma unroll
    for (int nt = 0; nt < 4; nt++)
        #pragma unroll
        for (int q = 0; q < 4; q++) c[nt][q] = 0.f;

    const int ar = tid >> 1;             // row 0..127 (2 threads/row)
    const int kb = (tid & 1) * 16;       // k base: 0 or 16
    float4 pfa4[4];
    float4 pfb[2];

    auto prefetch = [&](int j) {
        const float* xp = &x[(rowBase + ar) * (size_t)N_IN + j * 32 + kb];
        #pragma unroll
        for (int q = 0; q < 4; q++) pfa4[q] = *(const float4*)(xp + q * 4);
        const float4* wb = (const float4*)g_w1t;
        #pragma unroll
        for (int q = 0; q < 2; q++) {
            int idx = q * 256 + tid;
            int n = idx >> 4, fi = idx & 15;
            pfb[q] = wb[(size_t)n * (N_IN / 2) + j * 16 + fi];
        }
    };
    auto store_stage = [&](int st) {
        float* ap = &a_s[st * 4608 + ar * 36 + kb];
        #pragma unroll
        for (int q = 0; q < 4; q++) {
            ap[q*4+0] = __uint_as_float(cvt_tf32(pfa4[q].x));
            ap[q*4+1] = __uint_as_float(cvt_tf32(pfa4[q].y));
            ap[q*4+2] = __uint_as_float(cvt_tf32(pfa4[q].z));
            ap[q*4+3] = __uint_as_float(cvt_tf32(pfa4[q].w));
        }
        #pragma unroll
        for (int q = 0; q < 2; q++) {
            int idx = q * 256 + tid;
            int n = idx >> 4, fi = idx & 15;
            *(float4*)&b_s[st * 1152 + n * 36 + fi * 2] = pfb[q];
        }
    };

    prefetch(0);
    store_stage(0);
    __syncthreads();
    prefetch(1);

    const int mr = wid * 16;
    for (int j = 0; j < 64; j++) {
        const int cur = j & 1, nxt = cur ^ 1;
        if (j < 63) store_stage(nxt);
        if (j < 62) prefetch(j + 2);
        const float* ab = &a_s[cur * 4608];
        const float2* bbp = &b_s[cur * 1152];
        #pragma unroll
        for (int ks = 0; ks < 4; ks++) {
            const int k0 = ks * 8;
            uint32_t a0 = __float_as_uint(ab[(mr + g    ) * 36 + k0 + tg    ]);
            uint32_t a1 = __float_as_uint(ab[(mr + g + 8) * 36 + k0 + tg    ]);
            uint32_t a2 = __float_as_uint(ab[(mr + g    ) * 36 + k0 + tg + 4]);
            uint32_t a3 = __float_as_uint(ab[(mr + g + 8) * 36 + k0 + tg + 4]);
            #pragma unroll
            for (int nt = 0; nt < 4; nt++) {
                float2 f0 = bbp[(nt*8 + g) * 36 + k0 + tg    ];
                float2 f1 = bbp[(nt*8 + g) * 36 + k0 + tg + 4];
                mma_tf32(c[nt][0], c[nt][1], c[nt][2], c[nt][3], a0, a1, a2, a3,
                         __float_as_uint(f0.x), __float_as_uint(f1.x));
                mma_tf32(c[nt][0], c[nt][1], c[nt][2], c[nt][3], a0, a1, a2, a3,
                         __float_as_uint(f0.y), __float_as_uint(f1.y));
            }
        }
        __syncthreads();
    }

    size_t r0 = rowBase + wid * 16 + g;
    size_t r1 = r0 + 8;
    #pragma unroll
    for (int nt = 0; nt < 4; nt++) {
        int col = nt * 8 + tg * 2;
        float v00 = 0.f, v01 = 0.f, v10 = 0.f, v11 = 0.f;
        if (col < HH) {
            v00 = fmaxf(c[nt][0] + bias_s[col],     0.f);
            v01 = fmaxf(c[nt][1] + bias_s[col + 1], 0.f);
            v10 = fmaxf(c[nt][2] + bias_s[col],     0.f);
            v11 = fmaxf(c[nt][3] + bias_s[col + 1], 0.f);
            *(float2*)&g_flat[r0 * HH + col] = make_float2(v00, v01);
            *(float2*)&g_flat[r1 * HH + col] = make_float2(v10, v11);
        }
        float s0 = v00 + v10, q0 = v00 * v00 + v10 * v10;
        float s1 = v01 + v11, q1 = v01 * v01 + v11 * v11;
        #pragma unroll
        for (int off = 4; off < 32; off <<= 1) {
            s0 += __shfl_xor_sync(0xffffffffu, s0, off);
            q0 += __shfl_xor_sync(0xffffffffu, q0, off);
            s1 += __shfl_xor_sync(0xffffffffu, s1, off);
            q1 += __shfl_xor_sync(0xffffffffu, q1, off);
        }
        if (g == 0) {
            red[(col    ) * 8 + wid]       = s0;
            red[(col + 1) * 8 + wid]       = s1;
            red[256 + (col    ) * 8 + wid] = q0;
            red[256 + (col + 1) * 8 + wid] = q1;
        }
    }
    __syncthreads();
    if (tid < HH) {
        float s = 0.f, q = 0.f;
        #pragma unroll
        for (int w = 0; w < 8; w++) { s += red[tid * 8 + w]; q += red[256 + tid * 8 + w]; }
        g_partial[blockIdx.x * 60 + tid]      = s;
        g_partial[blockIdx.x * 60 + 30 + tid] = q;
    }
}

// ---------------- BN finalize ----------------
__global__ void bn_stats_kernel()
{
    __shared__ float rs[2][HH][9];
    int c = threadIdx.x & 31;
    int g = threadIdx.x >> 5;
    if (c < HH) {
        float s = 0.f, q = 0.f;
        for (int p = g; p < 1024; p += 8) {
            s += g_partial[p * 60 + c];
            q += g_partial[p * 60 + 30 + c];
        }
        rs[0][c][g] = s; rs[1][c][g] = q;
    }
    __syncthreads();
    if (threadIdx.x < HH) {
        float s = 0.f, q = 0.f;
        #pragma unroll
        for (int g2 = 0; g2 < 8; g2++) { s += rs[0][threadIdx.x][g2]; q += rs[1][threadIdx.x][g2]; }
        const float n = (float)ROWS;
        float mu  = s / n;
        float var = q / n - mu * mu;
        g_mu[threadIdx.x]   = mu;
        g_rstd[threadIdx.x] = rsqrtf(var + 1e-5f);
    }
}

// ---------------- prep BN-folded Wih0 (after bn_stats) ----------------
// W'[k][j] = rstd[k]*Wih0[j][k];  c'[j] = bias0[j] - sum_k mu[k]*W'[k][j]
__global__ void prep_z0w_kernel(const float* __restrict__ Wih0,
                                const float* __restrict__ bias0)
{
    int j = threadIdx.x;   // 0..127
    float cs = 0.f;
    for (int k = 0; k < 32; k++) {
        float wv = 0.f;
        if (j < 120 && k < HH) wv = g_rstd[k] * Wih0[j * HH + k];
        uint32_t hb = cvt_tf32(wv);
        float lo = wv - __uint_as_float(hb);
        g_wz[(j * 32 + k) * 2]     = hb;
        g_wz[(j * 32 + k) * 2 + 1] = cvt_tf32(lo);
        if (k < HH) cs += g_mu[k] * wv;
    }
    g_c0v[j] = ((j < 120) ? bias0[j] : 0.f) - cs;
}

// ================= z0x GEMM: g_flat[131072,30] @ W'[30,120] + c' ============
#define OG_A_FL (128*36)
#define OG_B_FL (128*36*2)
#define OG_SMEM_BYTES ((OG_A_FL + OG_B_FL) * 4)

__global__ __launch_bounds__(256)
void z0x_mma_kernel()
{
    extern __shared__ __align__(16) float sm[];
    float*  a_s = sm;
    float2* b_s = (float2*)(sm + OG_A_FL);

    const int tid  = threadIdx.x;
    const int wid  = tid >> 5;
    const int lane = tid & 31;
    const int g    = lane >> 2;
    const int tg   = lane & 3;
    const size_t rb = (size_t)blockIdx.x * 128;

    for (int i = tid; i < 128 * 32; i += 256) {
        int r = i >> 5, k = i & 31;
        float v = (k < HH) ? g_flat[(rb + r) * HH + k] : 0.f;
        a_s[r * 36 + k] = __uint_as_float(cvt_tf32(v));
    }
    {
        const float4* wb = (const float4*)g_wz;   // 16 float4 per n
        #pragma unroll
        for (int q = 0; q < 8; q++) {
            int idx = q * 256 + tid;
            int n = idx >> 4, fi = idx & 15;
            float4 v = wb[(size_t)n * 16 + fi];
            *(float4*)&b_s[n * 36 + fi * 2] = v;
        }
    }

    float c[16][4];
    #pragma unroll
    for (int nt = 0; nt < 16; nt++) {
        float bv0 = g_c0v[nt * 8 + tg * 2];
        float bv1 = g_c0v[nt * 8 + tg * 2 + 1];
        c[nt][0] = bv0; c[nt][1] = bv1; c[nt][2] = bv0; c[nt][3] = bv1;
    }
    __syncthreads();

    const int mr = wid * 16;
    #pragma unroll
    for (int ks = 0; ks < 4; ks++) {
        const int k0 = ks * 8;
        uint32_t a0 = __float_as_uint(a_s[(mr + g    ) * 36 + k0 + tg    ]);
        uint32_t a1 = __float_as_uint(a_s[(mr + g + 8) * 36 + k0 + tg    ]);
        uint32_t a2 = __float_as_uint(a_s[(mr + g    ) * 36 + k0 + tg + 4]);
        uint32_t a3 = __float_as_uint(a_s[(mr + g + 8) * 36 + k0 + tg + 4]);
        #pragma unroll
        for (int nt = 0; nt < 16; nt++) {
            float2 f0 = b_s[(nt*8 + g) * 36 + k0 + tg    ];
            float2 f1 = b_s[(nt*8 + g) * 36 + k0 + tg + 4];
            mma_tf32(c[nt][0], c[nt][1], c[nt][2], c[nt][3], a0, a1, a2, a3,
                     __float_as_uint(f0.x), __float_as_uint(f1.x));
            mma_tf32(c[nt][0], c[nt][1], c[nt][2], c[nt][3], a0, a1, a2, a3,
                     __float_as_uint(f0.y), __float_as_uint(f1.y));
        }
    }

    size_t r0 = rb + wid * 16 + g;
    size_t r1 = r0 + 8;
    #pragma unroll
    for (int nt = 0; nt < 16; nt++) {
        int col = nt * 8 + tg * 2;
        *(float2*)&g_z0x[r0 * 128 + col] = make_float2(c[nt][0], c[nt][1]);
        *(float2*)&g_z0x[r1 * 128 + col] = make_float2(c[nt][2], c[nt][3]);
    }
}

// ---------------- LSTM v2: gate-quad shuffles, 1 barrier/step ----------------
// threads 0..127:  layer0, thread = unit*4 + gate; h-dot only (z0x precomputed)
// threads 128..383: layer1, thread = unit*8 + gate*2 + half (half0: y0-dot+bias, half1: h1-dot)
__global__ __launch_bounds__(384, 2)
void lstm_kernel2(const float* __restrict__ h0, const float* __restrict__ c0,
                  const float* __restrict__ Whh0,
                  const float* __restrict__ Wih1, const float* __restrict__ Whh1,
                  const float* __restrict__ bias1,
                  float* __restrict__ rnn_out)
{
    __shared__ float h0buf[2][32];
    __shared__ float h1buf[2][32];

    const int tid = threadIdx.x;
    const int b   = blockIdx.x;
    const size_t zbase = (size_t)b * SS * 128;

    if (tid < 32) {
        h0buf[1][tid] = (tid < HH) ? h0[b * HH + tid]           : 0.f;
        h1buf[0][tid] = (tid < HH) ? h0[BB * HH + b * HH + tid] : 0.f;
        h0buf[0][tid] = 0.f;
        h1buf[1][tid] = 0.f;
    }

    float w[30];
    float creg = 0.f;
    float pz = 0.f;
    int u, gd;
    if (tid < 128) {
        u = tid >> 2; gd = tid & 3;
        int j = gd * HH + u;
        #pragma unroll
        for (int k = 0; k < HH; k++) w[k] = (u < HH) ? Whh0[j * HH + k] : 0.f;
        if (gd == 0 && u < HH) creg = c0[b * HH + u];
        pz = g_z0x[zbase + j];                       // z0x for t=0
    } else {
        int tt = tid - 128;
        u = tt >> 3; gd = (tt >> 1) & 3;
        int half = tt & 1;
        int j = gd * HH + u;
        const float* W = half ? Whh1 : Wih1;
        #pragma unroll
        for (int k = 0; k < HH; k++) w[k] = (u < HH) ? W[j * HH + k] : 0.f;
        pz = (half == 0 && u < HH) ? bias1[j] : 0.f; // constant bias (half0)
        if ((tt & 7) == 0 && u < HH) creg = c0[BB * HH + b * HH + u];
    }
    __syncthreads();

    for (int t = 0; t <= SS; t++) {
        const int cur = t & 1, prev = cur ^ 1;
        if (tid < 128) {
            if (t < SS) {
                const int j = gd * HH + u;
                const float* hv = h0buf[prev];
                float z = pz, z2 = 0.f;
                #pragma unroll
                for (int k = 0; k < HH; k += 2) { z += w[k] * hv[k]; z2 += w[k+1] * hv[k+1]; }
                z += z2;
                if (t + 1 < SS) pz = g_z0x[zbase + (size_t)(t + 1) * 128 + j];
                float v1 = __shfl_xor_sync(0xffffffffu, z, 1);
                float v2 = __shfl_xor_sync(0xffffffffu, z, 2);
                float v3 = __shfl_xor_sync(0xffffffffu, v1, 2);
                if (gd == 0 && u < HH) {
                    float ig = hsig(z), fg = hsig(v1), gg = htanh(v2), og = hsig(v3);
                    creg = fg * creg + ig * gg;
                    h0buf[cur][u] = og * htanh(creg);
                }
            }
        } else {
            if (t >= 1) {
                const int tt = tid - 128;
                const int half = tt & 1;
                const float* src = half ? h1buf[prev] : h0buf[prev];
                float a = pz, a2 = 0.f;
                #pragma unroll
                for (int k = 0; k < HH; k += 2) { a += w[k] * src[k]; a2 += w[k+1] * src[k+1]; }
                a += a2;
                float s  = a + __shfl_xor_sync(0xffffffffu, a, 1);
                float v2 = __shfl_xor_sync(0xffffffffu, s, 2);
                float v4 = __shfl_xor_sync(0xffffffffu, s, 4);
                float v6 = __shfl_xor_sync(0xffffffffu, v2, 4);
                if ((tt & 7) == 0 && u < HH) {
                    float ig = hsig(s), fg = hsig(v2), gg = htanh(v4), og = hsig(v6);
                    creg = fg * creg + ig * gg;
                    float hh = og * htanh(creg);
                    h1buf[cur][u] = hh;
                    rnn_out[((size_t)b * SS + (t - 1)) * HH + u] = hh;
                }
            }
        }
        __syncthreads();
    }
}

// ================= output GEMM: tf32 mma.sync, 128x128 tiles =================
__global__ __launch_bounds__(256)
void out_mma_kernel(const float* __restrict__ rnn, const float* __restrict__ bout,
                    float* __restrict__ dorsal)
{
    extern __shared__ __align__(16) float sm[];
    float*  a_s = sm;
    float2* b_s = (float2*)(sm + OG_A_FL);

    const int tid  = threadIdx.x;
    const int wid  = tid >> 5;
    const int lane = tid & 31;
    const int g    = lane >> 2;
    const int tg   = lane & 3;
    const size_t rb = (size_t)(blockIdx.x >> 2) * 128;
    const int cb    = (blockIdx.x & 3) * 128;

    for (int i = tid; i < 128 * 32; i += 256) {
        int r = i >> 5, k = i & 31;
        float v = (k < HH) ? rnn[(rb + r) * HH + k] : 0.f;
        a_s[r * 36 + k] = __uint_as_float(cvt_tf32(v));
    }
    {
        const float4* wb = (const float4*)g_wot;
        #pragma unroll
        for (int q = 0; q < 8; q++) {
            int idx = q * 256 + tid;
            int n = idx >> 4, fi = idx & 15;
            float4 v = wb[(size_t)(cb + n) * 16 + fi];
            *(float4*)&b_s[n * 36 + fi * 2] = v;
        }
    }

    float c[16][4];
    #pragma unroll
    for (int nt = 0; nt < 16; nt++) {
        float bv0 = bout[cb + nt * 8 + tg * 2];
        float bv1 = bout[cb + nt * 8 + tg * 2 + 1];
        c[nt][0] = bv0; c[nt][1] = bv1; c[nt][2] = bv0; c[nt][3] = bv1;
    }
    __syncthreads();

    const int mr = wid * 16;
    #pragma unroll
    for (int ks = 0; ks < 4; ks++) {
        const int k0 = ks * 8;
        uint32_t a0 = __float_as_uint(a_s[(mr + g    ) * 36 + k0 + tg    ]);
        uint32_t a1 = __float_as_uint(a_s[(mr + g + 8) * 36 + k0 + tg    ]);
        uint32_t a2 = __float_as_uint(a_s[(mr + g    ) * 36 + k0 + tg + 4]);
        uint32_t a3 = __float_as_uint(a_s[(mr + g + 8) * 36 + k0 + tg + 4]);
        #pragma unroll
        for (int nt = 0; nt < 16; nt++) {
            float2 f0 = b_s[(nt*8 + g) * 36 + k0 + tg    ];
            float2 f1 = b_s[(nt*8 + g) * 36 + k0 + tg + 4];
            mma_tf32(c[nt][0], c[nt][1], c[nt][2], c[nt][3], a0, a1, a2, a3,
                     __float_as_uint(f0.x), __float_as_uint(f1.x));
            mma_tf32(c[nt][0], c[nt][1], c[nt][2], c[nt][3], a0, a1, a2, a3,
                     __float_as_uint(f0.y), __float_as_uint(f1.y));
        }
    }

    size_t r0 = rb + wid * 16 + g;
    size_t r1 = r0 + 8;
    #pragma unroll
    for (int nt = 0; nt < 16; nt++) {
        int col = cb + nt * 8 + tg * 2;
        *(float2*)&dorsal[r0 * N_OUT + col] = make_float2(c[nt][0], c[nt][1]);
        *(float2*)&dorsal[r1 * N_OUT + col] = make_float2(c[nt][2], c[nt][3]);
    }
}

// ---------------- launch ----------------
extern "C" void kernel_launch(void* const* d_in, const int* in_sizes, int n_in,
                              void* d_out, int out_size)
{
    const float* x     = (const float*)d_in[0];
    const float* h0    = (const float*)d_in[1];
    const float* c0    = (const float*)d_in[2];
    const float* W1    = (const float*)d_in[3];
    const float* b1    = (const float*)d_in[4];
    const float* Wih0  = (const float*)d_in[5];
    const float* Whh0  = (const float*)d_in[6];
    const float* bias0 = (const float*)d_in[7];
    const float* Wih1  = (const float*)d_in[8];
    const float* Whh1  = (const float*)d_in[9];
    const float* bias1 = (const float*)d_in[10];
    const float* Wout  = (const float*)d_in[11];
    const float* bout  = (const float*)d_in[12];

    float* out    = (float*)d_out;
    float* dorsal = out;
    float* rnn    = out + (size_t)ROWS * N_OUT;

    cudaFuncSetAttribute(fc1_mma_kernel, cudaFuncAttributeMaxDynamicSharedMemorySize,
                         FC1_SMEM_BYTES);
    cudaFuncSetAttribute(z0x_mma_kernel, cudaFuncAttributeMaxDynamicSharedMemorySize,
                         OG_SMEM_BYTES);
    cudaFuncSetAttribute(out_mma_kernel, cudaFuncAttributeMaxDynamicSharedMemorySize,
                         OG_SMEM_BYTES);

    prep_w_kernel<<<(32 * N_IN + N_OUT * 32) / 256, 256>>>(W1, Wout);
    fc1_mma_kernel<<<ROWS / 128, 256, FC1_SMEM_BYTES>>>(x, b1);
    bn_stats_kernel<<<1, 256>>>();
    prep_z0w_kernel<<<1, 128>>>(Wih0, bias0);
    z0x_mma_kernel<<<ROWS / 128, 256, OG_SMEM_BYTES>>>();
    lstm_kernel2<<<BB, 384>>>(h0, c0, Whh0, Wih1, Whh1, bias1, rnn);
    out_mma_kernel<<<(ROWS / 128) * (N_OUT / 128), 256, OG_SMEM_BYTES>>>(rnn, bout, dorsal);
}

// round 8
// speedup vs baseline: 1.2679x; 1.2679x over previous
#include <cuda_runtime.h>
#include <cstdint>

#define BB 256
#define SS 512
#define N_IN 2048
#define N_OUT 512
#define HH 30
#define ROWS (BB*SS)   // 131072

// ---------------- device scratch ----------------
__device__ float g_flat[(size_t)ROWS * HH];
__device__ float g_partial[1024 * 64];
__device__ float g_mu[HH];
__device__ float g_rstd[HH];
// pre-converted weights (single rna-tf32), transposed [n][k]
__device__ uint32_t g_w1t[32 * N_IN];      // 256 KB
__device__ uint32_t g_wot[N_OUT * 32];     // 64 KB

// ---------------- helpers ----------------
__device__ __forceinline__ uint32_t cvt_tf32(float f) {
    uint32_t u; asm("cvt.rna.tf32.f32 %0, %1;" : "=r"(u) : "f"(f)); return u;
}
__device__ __forceinline__ void mma_tf32(float& c0, float& c1, float& c2, float& c3,
                                         uint32_t a0, uint32_t a1, uint32_t a2, uint32_t a3,
                                         uint32_t b0, uint32_t b1) {
    asm volatile(
        "mma.sync.aligned.m16n8k8.row.col.f32.tf32.tf32.f32 "
        "{%0,%1,%2,%3},{%4,%5,%6,%7},{%8,%9},{%0,%1,%2,%3};"
        : "+f"(c0), "+f"(c1), "+f"(c2), "+f"(c3)
        : "r"(a0), "r"(a1), "r"(a2), "r"(a3), "r"(b0), "r"(b1));
}
__device__ __forceinline__ float htanh(float x) {
    float r; asm("tanh.approx.f32 %0,%1;" : "=f"(r) : "f"(x)); return r;
}
__device__ __forceinline__ float hsig(float x) {
    return fmaf(htanh(x * 0.5f), 0.5f, 0.5f);
}

// ---------------- prep: convert W1/Wout to tf32, transposed ----------
__global__ __launch_bounds__(256)
void prep_w_kernel(const float* __restrict__ W1, const float* __restrict__ Wout)
{
    int i = blockIdx.x * 256 + threadIdx.x;
    if (i < 32 * N_IN) {
        int k = i >> 5, n = i & 31;
        float w = (n < HH) ? W1[(size_t)k * HH + n] : 0.f;
        g_w1t[n * N_IN + k] = cvt_tf32(w);
    }
    int j = i - 32 * N_IN;
    if (j >= 0 && j < N_OUT * 32) {
        int n = j >> 5, k = j & 31;
        float w = (k < HH) ? Wout[(size_t)k * N_OUT + n] : 0.f;
        g_wot[n * 32 + k] = cvt_tf32(w);
    }
}

// ================= fc1: tf32 mma.sync, double-buffered =================
// C[131072,30] = X @ W1; +bias, ReLU, BN partials.
// smem (floats): A[2][128][36] | B[2][32][36] | bias[32] | red[2*256]
#define FC1_A_FL (2*128*36)
#define FC1_B_FL (2*32*36)
#define FC1_SMEM_BYTES ((FC1_A_FL + FC1_B_FL + 32 + 512) * 4)

__global__ __launch_bounds__(256)
void fc1_mma_kernel(const float* __restrict__ x, const float* __restrict__ b1)
{
    extern __shared__ __align__(16) float sm[];
    float* a_s    = sm;                               // [2][128][36]
    float* b_s    = sm + FC1_A_FL;                    // [2][32][36]
    float* bias_s = sm + FC1_A_FL + FC1_B_FL;         // [32]
    float* red    = bias_s + 32;                      // [2][256]

    const int tid  = threadIdx.x;
    const int wid  = tid >> 5;
    const int lane = tid & 31;
    const int g    = lane >> 2;
    const int tg   = lane & 3;
    const size_t rowBase = (size_t)blockIdx.x * 128;

    if (tid < 32) bias_s[tid] = (tid < HH) ? b1[tid] : 0.f;

    float c[4][4];
    #pragma unroll
    for (int nt = 0; nt < 4; nt++)
        #pragma unroll
        for (int q = 0; q < 4; q++) c[nt][q] = 0.f;

    const int ar = tid >> 1;             // row 0..127 (2 threads/row)
    const int kb = (tid & 1) * 16;       // k base: 0 or 16
    const int bn = tid >> 3;             // B: n 0..31
    const int bf = tid & 7;              // B: float4 idx 0..7
    float4 pfa4[4];
    float4 pfb;

    auto prefetch = [&](int j) {
        const float* xp = &x[(rowBase + ar) * (size_t)N_IN + j * 32 + kb];
        #pragma unroll
        for (int q = 0; q < 4; q++) pfa4[q] = *(const float4*)(xp + q * 4);
        const float4* wb = (const float4*)g_w1t;          // per n: N_IN/4 float4
        pfb = wb[(size_t)bn * (N_IN / 4) + j * 8 + bf];
    };
    auto store_stage = [&](int st) {
        float* ap = &a_s[st * 4608 + ar * 36 + kb];
        #pragma unroll
        for (int q = 0; q < 4; q++) {
            ap[q*4+0] = __uint_as_float(cvt_tf32(pfa4[q].x));
            ap[q*4+1] = __uint_as_float(cvt_tf32(pfa4[q].y));
            ap[q*4+2] = __uint_as_float(cvt_tf32(pfa4[q].z));
            ap[q*4+3] = __uint_as_float(cvt_tf32(pfa4[q].w));
        }
        *(float4*)&b_s[st * 1152 + bn * 36 + bf * 4] = pfb;
    };

    prefetch(0);
    store_stage(0);
    __syncthreads();
    prefetch(1);

    const int mr = wid * 16;
    for (int j = 0; j < 64; j++) {
        const int cur = j & 1, nxt = cur ^ 1;
        if (j < 63) store_stage(nxt);
        if (j < 62) prefetch(j + 2);
        const float* ab  = &a_s[cur * 4608];
        const float* bbp = &b_s[cur * 1152];
        #pragma unroll
        for (int ks = 0; ks < 4; ks++) {
            const int k0 = ks * 8;
            uint32_t a0 = __float_as_uint(ab[(mr + g    ) * 36 + k0 + tg    ]);
            uint32_t a1 = __float_as_uint(ab[(mr + g + 8) * 36 + k0 + tg    ]);
            uint32_t a2 = __float_as_uint(ab[(mr + g    ) * 36 + k0 + tg + 4]);
            uint32_t a3 = __float_as_uint(ab[(mr + g + 8) * 36 + k0 + tg + 4]);
            #pragma unroll
            for (int nt = 0; nt < 4; nt++) {
                uint32_t b0 = __float_as_uint(bbp[(nt*8 + g) * 36 + k0 + tg    ]);
                uint32_t b1 = __float_as_uint(bbp[(nt*8 + g) * 36 + k0 + tg + 4]);
                mma_tf32(c[nt][0], c[nt][1], c[nt][2], c[nt][3], a0, a1, a2, a3, b0, b1);
            }
        }
        __syncthreads();
    }

    // epilogue: bias + ReLU + store + BN partials
    size_t r0 = rowBase + wid * 16 + g;
    size_t r1 = r0 + 8;
    #pragma unroll
    for (int nt = 0; nt < 4; nt++) {
        int col = nt * 8 + tg * 2;
        float v00 = 0.f, v01 = 0.f, v10 = 0.f, v11 = 0.f;
        if (col < HH) {
            v00 = fmaxf(c[nt][0] + bias_s[col],     0.f);
            v01 = fmaxf(c[nt][1] + bias_s[col + 1], 0.f);
            v10 = fmaxf(c[nt][2] + bias_s[col],     0.f);
            v11 = fmaxf(c[nt][3] + bias_s[col + 1], 0.f);
            *(float2*)&g_flat[r0 * HH + col] = make_float2(v00, v01);
            *(float2*)&g_flat[r1 * HH + col] = make_float2(v10, v11);
        }
        float s0 = v00 + v10, q0 = v00 * v00 + v10 * v10;
        float s1 = v01 + v11, q1 = v01 * v01 + v11 * v11;
        #pragma unroll
        for (int off = 4; off < 32; off <<= 1) {
            s0 += __shfl_xor_sync(0xffffffffu, s0, off);
            q0 += __shfl_xor_sync(0xffffffffu, q0, off);
            s1 += __shfl_xor_sync(0xffffffffu, s1, off);
            q1 += __shfl_xor_sync(0xffffffffu, q1, off);
        }
        if (g == 0) {
            red[(col    ) * 8 + wid]       = s0;
            red[(col + 1) * 8 + wid]       = s1;
            red[256 + (col    ) * 8 + wid] = q0;
            red[256 + (col + 1) * 8 + wid] = q1;
        }
    }
    __syncthreads();
    if (tid < HH) {
        float s = 0.f, q = 0.f;
        #pragma unroll
        for (int w = 0; w < 8; w++) { s += red[tid * 8 + w]; q += red[256 + tid * 8 + w]; }
        g_partial[blockIdx.x * 60 + tid]      = s;
        g_partial[blockIdx.x * 60 + 30 + tid] = q;
    }
}

// ---------------- BN finalize ----------------
__global__ void bn_stats_kernel()
{
    __shared__ float rs[2][HH][9];
    int c = threadIdx.x & 31;
    int g = threadIdx.x >> 5;
    if (c < HH) {
        float s = 0.f, q = 0.f;
        for (int p = g; p < 1024; p += 8) {
            s += g_partial[p * 60 + c];
            q += g_partial[p * 60 + 30 + c];
        }
        rs[0][c][g] = s; rs[1][c][g] = q;
    }
    __syncthreads();
    if (threadIdx.x < HH) {
        float s = 0.f, q = 0.f;
        #pragma unroll
        for (int g2 = 0; g2 < 8; g2++) { s += rs[0][threadIdx.x][g2]; q += rs[1][threadIdx.x][g2]; }
        const float n = (float)ROWS;
        float mu  = s / n;
        float var = q / n - mu * mu;
        g_mu[threadIdx.x]   = mu;
        g_rstd[threadIdx.x] = rsqrtf(var + 1e-5f);
    }
}

// ---------------- LSTM (R6-proven: scalar dots + MUFU tanh) ----------------
#define LSTM_THREADS 256
#define LSTM_SMEM_FLOATS (SS*32 + 32 + 32 + 32 + 128 + 128 + 32 + 32)
#define LSTM_SMEM_BYTES  (LSTM_SMEM_FLOATS * 4)

__device__ __forceinline__ float dot_step(const float* __restrict__ xv,
                                          const float* __restrict__ hv,
                                          const float (&wi)[32], const float (&wh)[32],
                                          float bj)
{
    const float4* x4 = (const float4*)xv;
    const float4* h4 = (const float4*)hv;
    float a0 = bj, a1 = 0.f, a2 = 0.f, a3 = 0.f;
    float b0 = 0.f, b1 = 0.f, b2 = 0.f, b3 = 0.f;
    #pragma unroll
    for (int q = 0; q < 8; q++) {
        float4 xq = x4[q];
        a0 += wi[4*q+0] * xq.x; a1 += wi[4*q+1] * xq.y;
        a2 += wi[4*q+2] * xq.z; a3 += wi[4*q+3] * xq.w;
        float4 hq = h4[q];
        b0 += wh[4*q+0] * hq.x; b1 += wh[4*q+1] * hq.y;
        b2 += wh[4*q+2] * hq.z; b3 += wh[4*q+3] * hq.w;
    }
    return ((a0 + a1) + (a2 + a3)) + ((b0 + b1) + (b2 + b3));
}

__global__ __launch_bounds__(LSTM_THREADS, 2)
void lstm_kernel(const float* __restrict__ h0, const float* __restrict__ c0,
                 const float* __restrict__ Wih0, const float* __restrict__ Whh0,
                 const float* __restrict__ bias0,
                 const float* __restrict__ Wih1, const float* __restrict__ Whh1,
                 const float* __restrict__ bias1,
                 float* __restrict__ rnn_out)
{
    extern __shared__ __align__(16) float lsm[];
    float* xs    = lsm;                    // [512][32]
    float* h0s   = lsm + SS * 32;          // [32]
    float* h1s   = h0s + 32;               // [32]
    float* y0s   = h1s + 32;               // [32]
    float* z0s   = y0s + 32;               // [128]
    float* z1s   = z0s + 128;              // [128]
    float* mus   = z1s + 128;              // [32]
    float* rstds = mus + 32;               // [32]

    const int tid = threadIdx.x;
    const int b   = blockIdx.x;

    if (tid < 32) {
        mus[tid]   = (tid < HH) ? g_mu[tid]   : 0.f;
        rstds[tid] = (tid < HH) ? g_rstd[tid] : 0.f;
        h0s[tid] = (tid < HH) ? h0[b * HH + tid]            : 0.f;
        h1s[tid] = (tid < HH) ? h0[BB * HH + b * HH + tid]  : 0.f;
        y0s[tid] = 0.f;
    }
    __syncthreads();

    const float* fb = g_flat + (size_t)b * (SS * HH);
    for (int i = tid; i < SS * 32; i += LSTM_THREADS) {
        int s = i >> 5, k = i & 31;
        xs[i] = (k < HH) ? (fb[s * HH + k] - mus[k]) * rstds[k] : 0.f;
    }

    float wi[32], wh[32];
    float bj = 0.f;
    #pragma unroll
    for (int k = 0; k < 32; k++) { wi[k] = 0.f; wh[k] = 0.f; }
    if (tid < 120) {
        #pragma unroll
        for (int k = 0; k < HH; k++) {
            wi[k] = Wih0[tid * HH + k];
            wh[k] = Whh0[tid * HH + k];
        }
        bj = bias0[tid];
    } else if (tid >= 128 && tid < 248) {
        int j = tid - 128;
        #pragma unroll
        for (int k = 0; k < HH; k++) {
            wi[k] = Wih1[j * HH + k];
            wh[k] = Whh1[j * HH + k];
        }
        bj = bias1[j];
    }

    float creg = 0.f;
    if (tid < HH)                          creg = c0[b * HH + tid];
    else if (tid >= 128 && tid < 128+HH)   creg = c0[BB * HH + b * HH + (tid - 128)];

    __syncthreads();

    for (int t = 0; t <= SS; t++) {
        if (t < SS && tid < 120) {
            z0s[tid] = dot_step(xs + t * 32, h0s, wi, wh, bj);
        } else if (t >= 1 && tid >= 128 && tid < 248) {
            z1s[tid - 128] = dot_step(y0s, h1s, wi, wh, bj);
        }
        __syncthreads();
        if (t < SS && tid < HH) {
            float ig = hsig(z0s[tid]);
            float fg = hsig(z0s[30 + tid]);
            float gg = htanh(z0s[60 + tid]);
            float og = hsig(z0s[90 + tid]);
            creg = fg * creg + ig * gg;
            float hh = og * htanh(creg);
            h0s[tid] = hh;
            y0s[tid] = hh;
        } else if (t >= 1 && tid >= 128 && tid < 128 + HH) {
            int u = tid - 128;
            float ig = hsig(z1s[u]);
            float fg = hsig(z1s[30 + u]);
            float gg = htanh(z1s[60 + u]);
            float og = hsig(z1s[90 + u]);
            creg = fg * creg + ig * gg;
            float hh = og * htanh(creg);
            h1s[u] = hh;
            rnn_out[((size_t)b * SS + (t - 1)) * HH + u] = hh;
        }
        __syncthreads();
    }
}

// ================= output GEMM: tf32 mma.sync, 128x128 tiles =================
#define OG_A_FL (128*36)
#define OG_B_FL (128*36)
#define OG_SMEM_BYTES ((OG_A_FL + OG_B_FL) * 4)

__global__ __launch_bounds__(256)
void out_mma_kernel(const float* __restrict__ rnn, const float* __restrict__ bout,
                    float* __restrict__ dorsal)
{
    extern __shared__ __align__(16) float sm[];
    float* a_s = sm;                 // [128][36]
    float* b_s = sm + OG_A_FL;       // [128][36]

    const int tid  = threadIdx.x;
    const int wid  = tid >> 5;
    const int lane = tid & 31;
    const int g    = lane >> 2;
    const int tg   = lane & 3;
    const size_t rb = (size_t)(blockIdx.x >> 2) * 128;
    const int cb    = (blockIdx.x & 3) * 128;

    for (int i = tid; i < 128 * 32; i += 256) {
        int r = i >> 5, k = i & 31;
        float v = (k < HH) ? rnn[(rb + r) * HH + k] : 0.f;
        a_s[r * 36 + k] = __uint_as_float(cvt_tf32(v));
    }
    {
        const float4* wb = (const float4*)g_wot;   // 8 float4 per n
        #pragma unroll
        for (int q = 0; q < 4; q++) {
            int idx = q * 256 + tid;               // 0..1023
            int n = idx >> 3, fi = idx & 7;
            float4 v = wb[(size_t)(cb + n) * 8 + fi];
            *(float4*)&b_s[n * 36 + fi * 4] = v;
        }
    }

    float c[16][4];
    #pragma unroll
    for (int nt = 0; nt < 16; nt++) {
        float bv0 = bout[cb + nt * 8 + tg * 2];
        float bv1 = bout[cb + nt * 8 + tg * 2 + 1];
        c[nt][0] = bv0; c[nt][1] = bv1; c[nt][2] = bv0; c[nt][3] = bv1;
    }
    __syncthreads();

    const int mr = wid * 16;
    #pragma unroll
    for (int ks = 0; ks < 4; ks++) {
        const int k0 = ks * 8;
        uint32_t a0 = __float_as_uint(a_s[(mr + g    ) * 36 + k0 + tg    ]);
        uint32_t a1 = __float_as_uint(a_s[(mr + g + 8) * 36 + k0 + tg    ]);
        uint32_t a2 = __float_as_uint(a_s[(mr + g    ) * 36 + k0 + tg + 4]);
        uint32_t a3 = __float_as_uint(a_s[(mr + g + 8) * 36 + k0 + tg + 4]);
        #pragma unroll
        for (int nt = 0; nt < 16; nt++) {
            uint32_t b0 = __float_as_uint(b_s[(nt*8 + g) * 36 + k0 + tg    ]);
            uint32_t b1 = __float_as_uint(b_s[(nt*8 + g) * 36 + k0 + tg + 4]);
            mma_tf32(c[nt][0], c[nt][1], c[nt][2], c[nt][3], a0, a1, a2, a3, b0, b1);
        }
    }

    size_t r0 = rb + wid * 16 + g;
    size_t r1 = r0 + 8;
    #pragma unroll
    for (int nt = 0; nt < 16; nt++) {
        int col = cb + nt * 8 + tg * 2;
        *(float2*)&dorsal[r0 * N_OUT + col] = make_float2(c[nt][0], c[nt][1]);
        *(float2*)&dorsal[r1 * N_OUT + col] = make_float2(c[nt][2], c[nt][3]);
    }
}

// ---------------- launch ----------------
extern "C" void kernel_launch(void* const* d_in, const int* in_sizes, int n_in,
                              void* d_out, int out_size)
{
    const float* x     = (const float*)d_in[0];
    const float* h0    = (const float*)d_in[1];
    const float* c0    = (const float*)d_in[2];
    const float* W1    = (const float*)d_in[3];
    const float* b1    = (const float*)d_in[4];
    const float* Wih0  = (const float*)d_in[5];
    const float* Whh0  = (const float*)d_in[6];
    const float* bias0 = (const float*)d_in[7];
    const float* Wih1  = (const float*)d_in[8];
    const float* Whh1  = (const float*)d_in[9];
    const float* bias1 = (const float*)d_in[10];
    const float* Wout  = (const float*)d_in[11];
    const float* bout  = (const float*)d_in[12];

    float* out    = (float*)d_out;
    float* dorsal = out;
    float* rnn    = out + (size_t)ROWS * N_OUT;

    cudaFuncSetAttribute(fc1_mma_kernel, cudaFuncAttributeMaxDynamicSharedMemorySize,
                         FC1_SMEM_BYTES);
    cudaFuncSetAttribute(out_mma_kernel, cudaFuncAttributeMaxDynamicSharedMemorySize,
                         OG_SMEM_BYTES);
    cudaFuncSetAttribute(lstm_kernel, cudaFuncAttributeMaxDynamicSharedMemorySize,
                         LSTM_SMEM_BYTES);

    prep_w_kernel<<<(32 * N_IN + N_OUT * 32) / 256, 256>>>(W1, Wout);
    fc1_mma_kernel<<<ROWS / 128, 256, FC1_SMEM_BYTES>>>(x, b1);
    bn_stats_kernel<<<1, 256>>>();
    lstm_kernel<<<BB, LSTM_THREADS, LSTM_SMEM_BYTES>>>(h0, c0, Wih0, Whh0, bias0,
                                                       Wih1, Whh1, bias1, rnn);
    out_mma_kernel<<<(ROWS / 128) * (N_OUT / 128), 256, OG_SMEM_BYTES>>>(rnn, bout, dorsal);
}